// round 11
// baseline (speedup 1.0000x reference)
#include <cuda_runtime.h>
#include <cuda_bf16.h>
#include <math.h>
#include <stdint.h>

// ---------------- problem constants ----------------
#define BB   256
#define TT   512
#define HH   1024
#define NCTA 128
#define NTHR 256      // 8 warps = 4 pairs; pair = {wmh0, wmh1} x 16 batch cols

// 128 CTAs = 32 mi (32 neurons) x 4 nb (64 batch); full K per CTA.
// SMEM: A frags (W hi 64K | lo 64K) | per-pair B bufs 4 x 3 x 8K (triple buffer)
#define OFF_ALO 65536
#define OFF_B   131072
#define SMEM_SZ (OFF_B + 4 * 3 * 8192)   // 229376 <= 227KB cap

// ---------------- device globals ----------------
// h in fused B-frag order: [buf][nb][kk 64][oct 8][lane 32] uint4 =
//   (hi slot0, hi slot1, lo slot0, lo slot1); each u32 = bf16 pair (par0,par1)
__device__ __align__(16) uint4 g_hb[2][4][64][8][32];    // 4 MB
__device__ volatile int g_dw[NCTA * 4];                  // per (cta, pair) flags
__device__ volatile int g_flags[NCTA];                   // one-time init barrier

__device__ __forceinline__ uint32_t pack_bf(float x, float y) {
    __nv_bfloat162 v = __floats2bfloat162_rn(x, y);
    return *reinterpret_cast<uint32_t*>(&v);
}
__device__ __forceinline__ unsigned short bhi(float x) {
    return __bfloat16_as_ushort(__float2bfloat16(x));
}
__device__ __forceinline__ float bup(unsigned short u) {
    return __bfloat162float(__ushort_as_bfloat16(u));
}
__device__ __forceinline__ void mma16816(float* c, const uint32_t* a,
                                         const uint32_t* b) {
    asm volatile(
        "mma.sync.aligned.m16n8k16.row.col.f32.bf16.bf16.f32 "
        "{%0,%1,%2,%3}, {%4,%5,%6,%7}, {%8,%9}, {%0,%1,%2,%3};"
        : "+f"(c[0]), "+f"(c[1]), "+f"(c[2]), "+f"(c[3])
        : "r"(a[0]), "r"(a[1]), "r"(a[2]), "r"(a[3]), "r"(b[0]), "r"(b[1]));
}
__device__ __forceinline__ float ftanh(float x) {
    float e = __expf(2.f * x);
    return 1.f - __fdividef(2.f, e + 1.f);
}

extern "C" __global__ void __launch_bounds__(NTHR, 1)
rnn_decoder_kernel(const float* __restrict__ init_in,   // [B,1]
                   const float* __restrict__ hidden0,   // [B,H]
                   const float* __restrict__ targets,   // [T,B,1]
                   const float* __restrict__ W_ih,      // [H,1]
                   const float* __restrict__ W_hh,      // [H,H]
                   const float* __restrict__ b_ih,      // [H]
                   const float* __restrict__ b_hh,      // [H]
                   const float* __restrict__ W_out,     // [1,H]
                   const float* __restrict__ b_out,     // [1]
                   float* __restrict__ out)             // [T,B,1]
{
    extern __shared__ __align__(16) char smem[];
    uint32_t sb;
    asm("{ .reg .u64 t; cvta.to.shared.u64 t, %1; cvt.u32.u64 %0, t; }"
        : "=r"(sb) : "l"(smem));

    const int tid  = threadIdx.x;
    const int cta  = blockIdx.x;
    const int wid  = tid >> 5;
    const int lane = tid & 31;
    const int g    = lane >> 2;
    const int tq   = lane & 3;
    const int wmh  = wid & 1;            // M half (16 rows) within pair
    const int w    = wid >> 1;           // pair id 0..3 (16 batch cols each)

    const int mi  = cta >> 2;            // 0..31
    const int nb  = cta & 3;             // 0..3
    const int m0  = mi * 32;
    const int bb0 = nb * 64;

    const int base_g = g_flags[cta];
    const int base_d = g_dw[cta * 4 + w];

    // ---- one-time: A fragments (W hi+lo) in exact mma lane order ----
    {
        const int r0 = m0 + wmh * 16 + g;
        const int r1 = r0 + 8;
        const int ks = wid >> 1;                         // kk slot 0..3
        for (int jj = 0; jj < 16; jj++) {
            const int kk = ks + 4 * jj;                  // 0..63
            const int c  = kk * 16 + 2 * tq;
            float w00 = W_hh[(size_t)r0 * HH + c];
            float w01 = W_hh[(size_t)r0 * HH + c + 1];
            float w04 = W_hh[(size_t)r0 * HH + c + 8];
            float w05 = W_hh[(size_t)r0 * HH + c + 9];
            float w10 = W_hh[(size_t)r1 * HH + c];
            float w11 = W_hh[(size_t)r1 * HH + c + 1];
            float w14 = W_hh[(size_t)r1 * HH + c + 8];
            float w15 = W_hh[(size_t)r1 * HH + c + 9];
            uint4 hi, lo;
            hi.x = pack_bf(w00, w01);
            hi.y = pack_bf(w10, w11);
            hi.z = pack_bf(w04, w05);
            hi.w = pack_bf(w14, w15);
            lo.x = pack_bf(w00 - bup(bhi(w00)), w01 - bup(bhi(w01)));
            lo.y = pack_bf(w10 - bup(bhi(w10)), w11 - bup(bhi(w11)));
            lo.z = pack_bf(w04 - bup(bhi(w04)), w05 - bup(bhi(w05)));
            lo.w = pack_bf(w14 - bup(bhi(w14)), w15 - bup(bhi(w15)));
            const int ob = (wmh * 64 + kk) * 512 + lane * 16;
            *reinterpret_cast<uint4*>(smem + ob)           = hi;
            *reinterpret_cast<uint4*>(smem + OFF_ALO + ob) = lo;
        }
    }

    // ---- one-time: publish h0 slice (fused uint4 frags), even-g lanes ----
    if ((g & 1) == 0) {
#pragma unroll
        for (int o = 0; o < 2; o++)
#pragma unroll
            for (int c = 0; c < 2; c++) {
                const int col = bb0 + w * 16 + o * 8 + 2 * tq + c;
                const int rA = m0 + wmh * 16 + g;
                float va = hidden0[(size_t)col * HH + rA];
                float vb = hidden0[(size_t)col * HH + rA + 1];
                float vc = hidden0[(size_t)col * HH + rA + 8];
                float vd = hidden0[(size_t)col * HH + rA + 9];
                uint4 u;
                u.x = (uint32_t)bhi(va) | ((uint32_t)bhi(vb) << 16);
                u.y = (uint32_t)bhi(vc) | ((uint32_t)bhi(vd) << 16);
                u.z = pack_bf(va - bup(bhi(va)), vb - bup(bhi(vb)));
                u.w = pack_bf(vc - bup(bhi(vc)), vd - bup(bhi(vd)));
                g_hb[1][nb][mi * 2 + wmh][2 * w + o][(2 * tq + c) * 4 + (g >> 1)] = u;
            }
    }
    // ---- one-time: out init to b_out ----
    {
        const float bo = b_out[0];
#pragma unroll
        for (int k = 0; k < 4; k++) out[(size_t)cta * 1024 + k * 256 + tid] = bo;
    }

    // epilogue constants for my 2 rows / 4 cols
    const int r0g = m0 + wmh * 16 + g, r8g = r0g + 8;
    const float bias_g = b_ih[r0g] + b_hh[r0g], bias_8 = b_ih[r8g] + b_hh[r8g];
    const float wih_g = W_ih[r0g], wih_8 = W_ih[r8g];
    const float wout_g = W_out[r0g], wout_8 = W_out[r8g];

    // ---- one-time grid barrier ----
    __threadfence();
    __syncthreads();
    if (tid == 0) g_flags[cta] = base_g + 1;
    if (tid < 32) {
        const int tgt = base_g + 1;
        bool ok;
        do {
            int a = g_flags[tid];
            int b = g_flags[tid + 32];
            int c = g_flags[tid + 64];
            int d = g_flags[tid + 96];
            ok = (a >= tgt) & (b >= tgt) & (c >= tgt) & (d >= tgt);
        } while (!__all_sync(0xffffffffu, ok));
        __threadfence();
    }
    __syncthreads();

    const int barid = 1 + w;             // named barrier per pair (64 threads)

#pragma unroll 1
    for (int t = 0; t < TT; t++) {
        const int rbuf = (t + 1) & 1, wbuf = t & 1;
        const char* srcB = (const char*)&g_hb[rbuf][nb][0][2 * w][0];  // +kk*4096
        const int tgt = base_d + t;

        // x for my 4 cols (prefetch at step start)
        const float* xsrc = (t == 0) ? init_in : (targets + (size_t)(t - 1) * BB);
        float xv[2][2];
#pragma unroll
        for (int o = 0; o < 2; o++)
#pragma unroll
            for (int c = 0; c < 2; c++)
                xv[o][c] = __ldg(&xsrc[bb0 + w * 16 + o * 8 + 2 * tq + c]);

        // poll: chunk c needs producers mi'=4c..4c+3, pair w only (4 flags)
        auto poll = [&](int c) {
            const int fi = ((4 * c + (lane & 3)) * 4 + nb) * 4 + w;
            bool ok;
            do {
                ok = (lane < 4) ? (g_dw[fi] >= tgt) : true;
            } while (!__all_sync(0xffffffffu, ok));
            __threadfence();
        };
        // cp.async chunk j into buf (j%3); caller gates by duty warp
        auto cpchunk = [&](int j) {
            const uint32_t dst = sb + OFF_B + w * 24576 + (j % 3) * 8192;
            const char* src = srcB + (size_t)j * 8 * 4096;   // kk stride 4096
#pragma unroll
            for (int i = 0; i < 16; i++) {
                const int flat = i * 32 + lane;              // 0..511
                const int kkl  = flat >> 6;
                const int o01  = (flat >> 5) & 1;
                const int ln   = flat & 31;
                asm volatile("cp.async.cg.shared.global [%0], [%1], 16;"
                             :: "r"(dst + flat * 16),
                                "l"(src + (size_t)kkl * 4096 + o01 * 512 + ln * 16));
            }
            asm volatile("cp.async.commit_group;" ::: "memory");
        };

        // prologue: warp0 -> chunk0, warp1 -> chunk1 (parallel)
        if (wmh == 0) { poll(0); cpchunk(0); asm volatile("cp.async.wait_group 0;" ::: "memory"); }
        else          { poll(1); cpchunk(1); }
        asm volatile("bar.sync %0, 64;" :: "r"(barid) : "memory");

        float accH[2][4], accLa[2][4], accLb[2][4];
#pragma unroll
        for (int o = 0; o < 2; o++)
#pragma unroll
            for (int e = 0; e < 4; e++) {
                accH[o][e] = 0.f; accLa[o][e] = 0.f; accLb[o][e] = 0.f;
            }

#pragma unroll 1
        for (int j = 0; j < 8; j++) {
            // duty warp (parity j) prefetches chunk j+2 (distance 2)
            if (j < 6 && wmh == (j & 1)) { poll(j + 2); cpchunk(j + 2); }

            const int bB = OFF_B + w * 24576 + (j % 3) * 8192 + lane * 16;
#pragma unroll
            for (int k = 0; k < 8; k++) {
                const int kk = j * 8 + k;
                const int ab = (wmh * 64 + kk) * 512 + lane * 16;
                uint4 Ah = *reinterpret_cast<const uint4*>(smem + ab);
                uint4 Al = *reinterpret_cast<const uint4*>(smem + OFF_ALO + ab);
#pragma unroll
                for (int o = 0; o < 2; o++) {
                    uint4 V = *reinterpret_cast<const uint4*>(
                        smem + bB + (k * 2 + o) * 512);
                    uint32_t Bh[2] = {V.x, V.y};
                    uint32_t Bl[2] = {V.z, V.w};
                    mma16816(accH[o],  &Ah.x, Bh);
                    mma16816(accLa[o], &Al.x, Bh);
                    mma16816(accLb[o], &Ah.x, Bl);
                }
            }
            // warp of parity (j+1) drains its cp for chunk j+1 before the bar
            if (j < 7 && wmh == ((j + 1) & 1))
                asm volatile("cp.async.wait_group 0;" ::: "memory");
            asm volatile("bar.sync %0, 64;" :: "r"(barid) : "memory");
        }

        // ---- epilogue: tanh, PUBLISH FIRST, then y ----
        float hgv[2][2], h8v[2][2];
#pragma unroll
        for (int o = 0; o < 2; o++)
#pragma unroll
            for (int c = 0; c < 2; c++) {
                float pg = (accH[o][c] + accLa[o][c]) + accLb[o][c] +
                           fmaf(xv[o][c], wih_g, bias_g);
                float p8 = (accH[o][c + 2] + accLa[o][c + 2]) + accLb[o][c + 2] +
                           fmaf(xv[o][c], wih_8, bias_8);
                hgv[o][c] = ftanh(pg);
                h8v[o][c] = ftanh(p8);
            }

#pragma unroll
        for (int o = 0; o < 2; o++)
#pragma unroll
            for (int c = 0; c < 2; c++) {
                uint32_t P1 = (uint32_t)bhi(hgv[o][c]) | ((uint32_t)bhi(h8v[o][c]) << 16);
                uint32_t P2 = pack_bf(hgv[o][c] - bup(bhi(hgv[o][c])),
                                      h8v[o][c] - bup(bhi(h8v[o][c])));
                uint32_t q1 = __shfl_xor_sync(0xffffffffu, P1, 4);
                uint32_t q2 = __shfl_xor_sync(0xffffffffu, P2, 4);
                if ((g & 1) == 0) {
                    uint4 u;
                    u.x = __byte_perm(P1, q1, 0x5410);   // hi slot0: rows g,g+1
                    u.y = __byte_perm(P1, q1, 0x7632);   // hi slot1: rows g+8,g+9
                    u.z = __byte_perm(P2, q2, 0x5410);
                    u.w = __byte_perm(P2, q2, 0x7632);
                    g_hb[wbuf][nb][mi * 2 + wmh][2 * w + o]
                        [(2 * tq + c) * 4 + (g >> 1)] = u;
                }
            }
        __threadfence();
        asm volatile("bar.sync %0, 64;" :: "r"(barid) : "memory");
        if (wmh == 0 && lane == 0) g_dw[cta * 4 + w] = base_d + t + 1;

        // y partials after the flag (off the recurrence critical path)
        float yp[2][2];
#pragma unroll
        for (int o = 0; o < 2; o++)
#pragma unroll
            for (int c = 0; c < 2; c++)
                yp[o][c] = hgv[o][c] * wout_g + h8v[o][c] * wout_8;
#pragma unroll
        for (int off = 4; off < 32; off <<= 1)
#pragma unroll
            for (int o = 0; o < 2; o++)
#pragma unroll
                for (int c = 0; c < 2; c++)
                    yp[o][c] += __shfl_xor_sync(0xffffffffu, yp[o][c], off);
        if (lane < 4) {
#pragma unroll
            for (int o = 0; o < 2; o++)
#pragma unroll
                for (int c = 0; c < 2; c++)
                    atomicAdd(&out[(size_t)t * BB + bb0 + w * 16 + o * 8 + 2 * lane + c],
                              yp[o][c]);
        }
    }
}

extern "C" void kernel_launch(void* const* d_in, const int* in_sizes, int n_in,
                              void* d_out, int out_size) {
    const float* init_in = (const float*)d_in[0];
    const float* hidden0 = (const float*)d_in[1];
    const float* targets = (const float*)d_in[2];
    const float* W_ih    = (const float*)d_in[3];
    const float* W_hh    = (const float*)d_in[4];
    const float* b_ih    = (const float*)d_in[5];
    const float* b_hh    = (const float*)d_in[6];
    const float* W_out   = (const float*)d_in[7];
    const float* b_out   = (const float*)d_in[8];
    float* out = (float*)d_out;

    cudaFuncSetAttribute(rnn_decoder_kernel,
                         cudaFuncAttributeMaxDynamicSharedMemorySize, SMEM_SZ);
    rnn_decoder_kernel<<<NCTA, NTHR, SMEM_SZ>>>(init_in, hidden0, targets, W_ih,
                                                W_hh, b_ih, b_hh, W_out, b_out,
                                                out);
}

// round 12
// speedup vs baseline: 1.3654x; 1.3654x over previous
#include <cuda_runtime.h>
#include <cuda_bf16.h>
#include <math.h>
#include <stdint.h>

// ---------------- problem constants ----------------
#define BB   256
#define TT   512
#define HH   1024
#define NCTA 128
#define NTHR 512      // 16 warps = 8 pairs; pair = {wmh0,wmh1} x 8 batch cols

// 128 CTAs = 32 mi (32 neurons) x 4 nb (64 batch); full K per CTA.
// SMEM: A frags (W hi 64K | lo 64K) | per-pair B bufs 8 x 2 x 4K
#define OFF_ALO 65536
#define OFF_B   131072
#define SMEM_SZ (OFF_B + 8 * 2 * 4096)   // 196608

// ---------------- device globals ----------------
// h in fused B-frag order: [buf][nb][kk 64][oct 8][lane 32] uint4 =
//   (hi slot0, hi slot1, lo slot0, lo slot1); each u32 = bf16 pair
__device__ __align__(16) uint4 g_hb[2][4][64][8][32];    // 4 MB
// per-warp publish flags: [nb][pair w][mi*2+wmh]  (chunk j -> 8 contiguous)
__device__ volatile int g_dw2[4][8][64];
__device__ volatile int g_flags[NCTA];                   // one-time init barrier

__device__ __forceinline__ uint32_t pack_bf(float x, float y) {
    __nv_bfloat162 v = __floats2bfloat162_rn(x, y);
    return *reinterpret_cast<uint32_t*>(&v);
}
__device__ __forceinline__ unsigned short bhi(float x) {
    return __bfloat16_as_ushort(__float2bfloat16(x));
}
__device__ __forceinline__ float bup(unsigned short u) {
    return __bfloat162float(__ushort_as_bfloat16(u));
}
__device__ __forceinline__ void mma16816(float* c, const uint32_t* a,
                                         const uint32_t* b) {
    asm volatile(
        "mma.sync.aligned.m16n8k16.row.col.f32.bf16.bf16.f32 "
        "{%0,%1,%2,%3}, {%4,%5,%6,%7}, {%8,%9}, {%0,%1,%2,%3};"
        : "+f"(c[0]), "+f"(c[1]), "+f"(c[2]), "+f"(c[3])
        : "r"(a[0]), "r"(a[1]), "r"(a[2]), "r"(a[3]), "r"(b[0]), "r"(b[1]));
}
__device__ __forceinline__ float ftanh(float x) {
    float e = __expf(2.f * x);
    return 1.f - __fdividef(2.f, e + 1.f);
}
__device__ __forceinline__ void ldvol4(int* r, const volatile int* p) {
    asm volatile("ld.volatile.global.v4.u32 {%0,%1,%2,%3}, [%4];"
                 : "=r"(r[0]), "=r"(r[1]), "=r"(r[2]), "=r"(r[3])
                 : "l"(p));
}

extern "C" __global__ void __launch_bounds__(NTHR, 1)
rnn_decoder_kernel(const float* __restrict__ init_in,   // [B,1]
                   const float* __restrict__ hidden0,   // [B,H]
                   const float* __restrict__ targets,   // [T,B,1]
                   const float* __restrict__ W_ih,      // [H,1]
                   const float* __restrict__ W_hh,      // [H,H]
                   const float* __restrict__ b_ih,      // [H]
                   const float* __restrict__ b_hh,      // [H]
                   const float* __restrict__ W_out,     // [1,H]
                   const float* __restrict__ b_out,     // [1]
                   float* __restrict__ out)             // [T,B,1]
{
    extern __shared__ __align__(16) char smem[];
    uint32_t sb;
    asm("{ .reg .u64 t; cvta.to.shared.u64 t, %1; cvt.u32.u64 %0, t; }"
        : "=r"(sb) : "l"(smem));

    const int tid  = threadIdx.x;
    const int cta  = blockIdx.x;
    const int wid  = tid >> 5;
    const int lane = tid & 31;
    const int g    = lane >> 2;
    const int tq   = lane & 3;
    const int wmh  = wid & 1;            // M half (16 rows) within pair
    const int w    = wid >> 1;           // pair id 0..7 (8 batch cols each)

    const int mi  = cta >> 2;            // 0..31
    const int nb  = cta & 3;             // 0..3
    const int m0  = mi * 32;
    const int bb0 = nb * 64;

    const int base_g = g_flags[cta];
    const int base_d = g_dw2[nb][w][mi * 2 + wmh];

    // ---- one-time: A fragments (W hi+lo) in exact mma lane order ----
    {
        const int r0 = m0 + wmh * 16 + g;
        const int r1 = r0 + 8;
        for (int jj = 0; jj < 8; jj++) {
            const int kk = w + 8 * jj;                   // 0..63
            const int c  = kk * 16 + 2 * tq;
            float w00 = W_hh[(size_t)r0 * HH + c];
            float w01 = W_hh[(size_t)r0 * HH + c + 1];
            float w04 = W_hh[(size_t)r0 * HH + c + 8];
            float w05 = W_hh[(size_t)r0 * HH + c + 9];
            float w10 = W_hh[(size_t)r1 * HH + c];
            float w11 = W_hh[(size_t)r1 * HH + c + 1];
            float w14 = W_hh[(size_t)r1 * HH + c + 8];
            float w15 = W_hh[(size_t)r1 * HH + c + 9];
            uint4 hi, lo;
            hi.x = pack_bf(w00, w01);
            hi.y = pack_bf(w10, w11);
            hi.z = pack_bf(w04, w05);
            hi.w = pack_bf(w14, w15);
            lo.x = pack_bf(w00 - bup(bhi(w00)), w01 - bup(bhi(w01)));
            lo.y = pack_bf(w10 - bup(bhi(w10)), w11 - bup(bhi(w11)));
            lo.z = pack_bf(w04 - bup(bhi(w04)), w05 - bup(bhi(w05)));
            lo.w = pack_bf(w14 - bup(bhi(w14)), w15 - bup(bhi(w15)));
            const int ob = (wmh * 64 + kk) * 512 + lane * 16;
            *reinterpret_cast<uint4*>(smem + ob)           = hi;
            *reinterpret_cast<uint4*>(smem + OFF_ALO + ob) = lo;
        }
    }

    // ---- one-time: publish h0 slice into g_hb[1] (512 uint4 per CTA) ----
    {
        const int pwmh = tid >> 8;                       // 0..1
        const int poct = (tid >> 5) & 7;                 // 0..7
        const int pln  = tid & 31;
        const int pcol = pln >> 2;                       // 0..7
        const int pg   = (pln & 3) * 2;                  // 0,2,4,6
        const int col  = bb0 + poct * 8 + pcol;
        const int rA   = m0 + pwmh * 16 + pg;
        float va = hidden0[(size_t)col * HH + rA];
        float vb = hidden0[(size_t)col * HH + rA + 1];
        float vc = hidden0[(size_t)col * HH + rA + 8];
        float vd = hidden0[(size_t)col * HH + rA + 9];
        uint4 u;
        u.x = (uint32_t)bhi(va) | ((uint32_t)bhi(vb) << 16);
        u.y = (uint32_t)bhi(vc) | ((uint32_t)bhi(vd) << 16);
        u.z = pack_bf(va - bup(bhi(va)), vb - bup(bhi(vb)));
        u.w = pack_bf(vc - bup(bhi(vc)), vd - bup(bhi(vd)));
        g_hb[1][nb][mi * 2 + pwmh][poct][pcol * 4 + (pg >> 1)] = u;
    }
    // ---- one-time: out init to b_out ----
    {
        const float bo = b_out[0];
        out[(size_t)cta * 1024 + tid]       = bo;
        out[(size_t)cta * 1024 + 512 + tid] = bo;
    }

    // epilogue constants for my 2 rows / 2 cols
    const int r0g = m0 + wmh * 16 + g, r8g = r0g + 8;
    const float bias_g = b_ih[r0g] + b_hh[r0g], bias_8 = b_ih[r8g] + b_hh[r8g];
    const float wih_g = W_ih[r0g], wih_8 = W_ih[r8g];
    const float wout_g = W_out[r0g], wout_8 = W_out[r8g];

    // ---- one-time grid barrier ----
    __threadfence();
    __syncthreads();
    if (tid == 0) g_flags[cta] = base_g + 1;
    if (tid < 32) {
        const int tgt = base_g + 1;
        bool ok;
        do {
            int a = g_flags[tid];
            int b = g_flags[tid + 32];
            int c = g_flags[tid + 64];
            int d = g_flags[tid + 96];
            ok = (a >= tgt) & (b >= tgt) & (c >= tgt) & (d >= tgt);
        } while (!__all_sync(0xffffffffu, ok));
        __threadfence();
    }
    __syncthreads();

    const int barid = 1 + w;             // named barrier per pair (64 threads)
    const int myflag = mi * 2 + wmh;

#pragma unroll 1
    for (int t = 0; t < TT; t++) {
        const int rbuf = (t + 1) & 1, wbuf = t & 1;
        const char* srcB = (const char*)&g_hb[rbuf][nb][0][0][0];
        const int tgt = base_d + t;

        // x for my 2 cols
        const float* xsrc = (t == 0) ? init_in : (targets + (size_t)(t - 1) * BB);
        const float xv0 = __ldg(&xsrc[bb0 + w * 8 + 2 * tq]);
        const float xv1 = __ldg(&xsrc[bb0 + w * 8 + 2 * tq + 1]);

        // poll: chunk c needs 8 contiguous warp-flags [nb][w][8c..8c+7]
        auto poll = [&](int c) {
            const volatile int* f = &g_dw2[nb][w][8 * c];
            int r[8];
            bool ok;
            do {
                ldvol4(r, f);
                ldvol4(r + 4, f + 4);
                ok = (r[0] >= tgt) & (r[1] >= tgt) & (r[2] >= tgt) & (r[3] >= tgt) &
                     (r[4] >= tgt) & (r[5] >= tgt) & (r[6] >= tgt) & (r[7] >= tgt);
            } while (!ok);
            __threadfence();
        };
        // cp.async chunk j (4 KB: kk 8j..8j+7, oct w) into parity p
        auto cpchunk = [&](int j, int p) {
            const uint32_t dst = sb + OFF_B + w * 8192 + p * 4096;
#pragma unroll
            for (int i = 0; i < 8; i++) {
                const int flat = i * 32 + lane;          // 0..255
                const int kkl  = flat >> 5;
                const int ln   = flat & 31;
                asm volatile("cp.async.cg.shared.global [%0], [%1], 16;"
                             :: "r"(dst + flat * 16),
                                "l"(srcB + (size_t)(((8 * j + kkl) * 8 + w) * 512 + ln * 16)));
            }
            asm volatile("cp.async.commit_group;" ::: "memory");
        };

        if (wmh == 0) {
            poll(0); cpchunk(0, 0);
            asm volatile("cp.async.wait_group 0;" ::: "memory");
        }
        asm volatile("bar.sync %0, 64;" :: "r"(barid) : "memory");

        float accH[4], accLa[4], accLb[4];
#pragma unroll
        for (int e = 0; e < 4; e++) { accH[e] = 0.f; accLa[e] = 0.f; accLb[e] = 0.f; }

#pragma unroll 1
        for (int j = 0; j < 8; j++) {
            asm volatile("bar.sync %0, 64;" :: "r"(barid) : "memory");
            if (j < 7 && wmh == 0) { poll(j + 1); cpchunk(j + 1, (j + 1) & 1); }

            const int bB = OFF_B + w * 8192 + (j & 1) * 4096 + lane * 16;
#pragma unroll
            for (int k = 0; k < 8; k++) {
                const int kk = j * 8 + k;
                const int ab = (wmh * 64 + kk) * 512 + lane * 16;
                uint4 Ah = *reinterpret_cast<const uint4*>(smem + ab);
                uint4 Al = *reinterpret_cast<const uint4*>(smem + OFF_ALO + ab);
                uint4 V  = *reinterpret_cast<const uint4*>(smem + bB + k * 512);
                uint32_t Bh[2] = {V.x, V.y};
                uint32_t Bl[2] = {V.z, V.w};
                mma16816(accH,  &Ah.x, Bh);
                mma16816(accLa, &Al.x, Bh);
                mma16816(accLb, &Ah.x, Bl);
            }
            if (j < 7 && wmh == 0)
                asm volatile("cp.async.wait_group 0;" ::: "memory");
        }

        // ---- epilogue (warp-autonomous): tanh, publish, flag, then y ----
        float hg0 = ftanh((accH[0] + accLa[0]) + accLb[0] + fmaf(xv0, wih_g, bias_g));
        float hg1 = ftanh((accH[1] + accLa[1]) + accLb[1] + fmaf(xv1, wih_g, bias_g));
        float h80 = ftanh((accH[2] + accLa[2]) + accLb[2] + fmaf(xv0, wih_8, bias_8));
        float h81 = ftanh((accH[3] + accLa[3]) + accLb[3] + fmaf(xv1, wih_8, bias_8));

        const float hgv[2] = {hg0, hg1};
        const float h8v[2] = {h80, h81};
#pragma unroll
        for (int c = 0; c < 2; c++) {
            uint32_t P1 = (uint32_t)bhi(hgv[c]) | ((uint32_t)bhi(h8v[c]) << 16);
            uint32_t P2 = pack_bf(hgv[c] - bup(bhi(hgv[c])),
                                  h8v[c] - bup(bhi(h8v[c])));
            uint32_t q1 = __shfl_xor_sync(0xffffffffu, P1, 4);
            uint32_t q2 = __shfl_xor_sync(0xffffffffu, P2, 4);
            if ((g & 1) == 0) {
                uint4 u;
                u.x = __byte_perm(P1, q1, 0x5410);   // hi slot0: rows g,g+1
                u.y = __byte_perm(P1, q1, 0x7632);   // hi slot1: rows g+8,g+9
                u.z = __byte_perm(P2, q2, 0x5410);
                u.w = __byte_perm(P2, q2, 0x7632);
                g_hb[wbuf][nb][mi * 2 + wmh][w][(2 * tq + c) * 4 + (g >> 1)] = u;
            }
        }
        __threadfence();
        __syncwarp();
        if (lane == 0) g_dw2[nb][w][myflag] = base_d + t + 1;

        // y partials after the flag (off the recurrence critical path)
        float yp0 = hg0 * wout_g + h80 * wout_8;
        float yp1 = hg1 * wout_g + h81 * wout_8;
#pragma unroll
        for (int off = 4; off < 32; off <<= 1) {
            yp0 += __shfl_xor_sync(0xffffffffu, yp0, off);
            yp1 += __shfl_xor_sync(0xffffffffu, yp1, off);
        }
        if (lane < 4) {
            atomicAdd(&out[(size_t)t * BB + bb0 + w * 8 + 2 * lane],     yp0);
            atomicAdd(&out[(size_t)t * BB + bb0 + w * 8 + 2 * lane + 1], yp1);
        }
    }
}

extern "C" void kernel_launch(void* const* d_in, const int* in_sizes, int n_in,
                              void* d_out, int out_size) {
    const float* init_in = (const float*)d_in[0];
    const float* hidden0 = (const float*)d_in[1];
    const float* targets = (const float*)d_in[2];
    const float* W_ih    = (const float*)d_in[3];
    const float* W_hh    = (const float*)d_in[4];
    const float* b_ih    = (const float*)d_in[5];
    const float* b_hh    = (const float*)d_in[6];
    const float* W_out   = (const float*)d_in[7];
    const float* b_out   = (const float*)d_in[8];
    float* out = (float*)d_out;

    cudaFuncSetAttribute(rnn_decoder_kernel,
                         cudaFuncAttributeMaxDynamicSharedMemorySize, SMEM_SZ);
    rnn_decoder_kernel<<<NCTA, NTHR, SMEM_SZ>>>(init_in, hidden0, targets, W_ih,
                                                W_hh, b_ih, b_hh, W_out, b_out,
                                                out);
}

// round 13
// speedup vs baseline: 1.5954x; 1.1684x over previous
#include <cuda_runtime.h>
#include <cuda_fp16.h>
#include <math.h>
#include <stdint.h>

// ---------------- problem constants ----------------
#define BB   256
#define TT   512
#define HH   1024
#define NCTA 128
#define NTHR 512      // 16 warps = 8 pairs; pair = {wmh0,wmh1} x 8 batch cols

// 128 CTAs = 32 mi (32 neurons) x 4 nb (64 batch); full K per CTA.
// SMEM: A frags (W hi 64K | lo 64K, fp16) | per-pair B bufs 8 x 2 x 4K
#define OFF_ALO 65536
#define OFF_B   131072
#define SMEM_SZ (OFF_B + 8 * 2 * 4096)   // 196608

// ---------------- device globals ----------------
// h in fp16 B-frag order: [buf][nb][kk 64][oct 8][lane 32] uint2 =
//   (slot0: rows pair, slot1: rows+8 pair)
__device__ __align__(16) uint2 g_hf[2][4][64][8][32];    // 2 MB
// per-warp publish flags: [nb][pair w][mi*2+wmh]; chunk c -> 16 contiguous
__device__ volatile int g_dw2[4][8][64];
__device__ volatile int g_flags[NCTA];                   // one-time init barrier

__device__ __forceinline__ uint32_t pack_hf(float x, float y) {
    __half2 v = __floats2half2_rn(x, y);                 // low = x, high = y
    return *reinterpret_cast<uint32_t*>(&v);
}
__device__ __forceinline__ unsigned short hbits(float x) {
    return __half_as_ushort(__float2half_rn(x));
}
__device__ __forceinline__ float hup(unsigned short u) {
    return __half2float(__ushort_as_half(u));
}
__device__ __forceinline__ void mma16816h(float* c, const uint32_t* a,
                                          const uint32_t* b) {
    asm volatile(
        "mma.sync.aligned.m16n8k16.row.col.f32.f16.f16.f32 "
        "{%0,%1,%2,%3}, {%4,%5,%6,%7}, {%8,%9}, {%0,%1,%2,%3};"
        : "+f"(c[0]), "+f"(c[1]), "+f"(c[2]), "+f"(c[3])
        : "r"(a[0]), "r"(a[1]), "r"(a[2]), "r"(a[3]), "r"(b[0]), "r"(b[1]));
}
__device__ __forceinline__ float ftanh(float x) {
    float e = __expf(2.f * x);
    return 1.f - __fdividef(2.f, e + 1.f);
}
__device__ __forceinline__ void ldvol4(int* r, const volatile int* p) {
    asm volatile("ld.volatile.global.v4.u32 {%0,%1,%2,%3}, [%4];"
                 : "=r"(r[0]), "=r"(r[1]), "=r"(r[2]), "=r"(r[3])
                 : "l"(p));
}

extern "C" __global__ void __launch_bounds__(NTHR, 1)
rnn_decoder_kernel(const float* __restrict__ init_in,   // [B,1]
                   const float* __restrict__ hidden0,   // [B,H]
                   const float* __restrict__ targets,   // [T,B,1]
                   const float* __restrict__ W_ih,      // [H,1]
                   const float* __restrict__ W_hh,      // [H,H]
                   const float* __restrict__ b_ih,      // [H]
                   const float* __restrict__ b_hh,      // [H]
                   const float* __restrict__ W_out,     // [1,H]
                   const float* __restrict__ b_out,     // [1]
                   float* __restrict__ out)             // [T,B,1]
{
    extern __shared__ __align__(16) char smem[];
    uint32_t sb;
    asm("{ .reg .u64 t; cvta.to.shared.u64 t, %1; cvt.u32.u64 %0, t; }"
        : "=r"(sb) : "l"(smem));

    const int tid  = threadIdx.x;
    const int cta  = blockIdx.x;
    const int wid  = tid >> 5;
    const int lane = tid & 31;
    const int g    = lane >> 2;
    const int tq   = lane & 3;
    const int wmh  = wid & 1;            // M half (16 rows) within pair
    const int w    = wid >> 1;           // pair id 0..7 (8 batch cols each)

    const int mi  = cta >> 2;            // 0..31
    const int nb  = cta & 3;             // 0..3
    const int m0  = mi * 32;
    const int bb0 = nb * 64;

    const int base_g = g_flags[cta];
    const int base_d = g_dw2[nb][w][mi * 2 + wmh];

    // ---- one-time: A fragments (W hi+lo fp16) in exact mma lane order ----
    {
        const int r0 = m0 + wmh * 16 + g;
        const int r1 = r0 + 8;
        for (int jj = 0; jj < 8; jj++) {
            const int kk = w + 8 * jj;                   // 0..63
            const int c  = kk * 16 + 2 * tq;
            float w00 = W_hh[(size_t)r0 * HH + c];
            float w01 = W_hh[(size_t)r0 * HH + c + 1];
            float w04 = W_hh[(size_t)r0 * HH + c + 8];
            float w05 = W_hh[(size_t)r0 * HH + c + 9];
            float w10 = W_hh[(size_t)r1 * HH + c];
            float w11 = W_hh[(size_t)r1 * HH + c + 1];
            float w14 = W_hh[(size_t)r1 * HH + c + 8];
            float w15 = W_hh[(size_t)r1 * HH + c + 9];
            uint4 hi, lo;
            hi.x = pack_hf(w00, w01);
            hi.y = pack_hf(w10, w11);
            hi.z = pack_hf(w04, w05);
            hi.w = pack_hf(w14, w15);
            lo.x = pack_hf(w00 - hup(hbits(w00)), w01 - hup(hbits(w01)));
            lo.y = pack_hf(w10 - hup(hbits(w10)), w11 - hup(hbits(w11)));
            lo.z = pack_hf(w04 - hup(hbits(w04)), w05 - hup(hbits(w05)));
            lo.w = pack_hf(w14 - hup(hbits(w14)), w15 - hup(hbits(w15)));
            const int ob = (wmh * 64 + kk) * 512 + lane * 16;
            *reinterpret_cast<uint4*>(smem + ob)           = hi;
            *reinterpret_cast<uint4*>(smem + OFF_ALO + ob) = lo;
        }
    }

    // ---- one-time: publish h0 slice into g_hf[1] (512 uint2 per CTA) ----
    {
        const int pwmh = tid >> 8;                       // 0..1
        const int poct = (tid >> 5) & 7;                 // 0..7
        const int pln  = tid & 31;
        const int pcol = pln >> 2;                       // 0..7
        const int pg   = (pln & 3) * 2;                  // 0,2,4,6
        const int col  = bb0 + poct * 8 + pcol;
        const int rA   = m0 + pwmh * 16 + pg;
        float va = hidden0[(size_t)col * HH + rA];
        float vb = hidden0[(size_t)col * HH + rA + 1];
        float vc = hidden0[(size_t)col * HH + rA + 8];
        float vd = hidden0[(size_t)col * HH + rA + 9];
        uint2 u;
        u.x = (uint32_t)hbits(va) | ((uint32_t)hbits(vb) << 16);
        u.y = (uint32_t)hbits(vc) | ((uint32_t)hbits(vd) << 16);
        g_hf[1][nb][mi * 2 + pwmh][poct][pcol * 4 + (pg >> 1)] = u;
    }
    // ---- one-time: out init to b_out ----
    {
        const float bo = b_out[0];
        out[(size_t)cta * 1024 + tid]       = bo;
        out[(size_t)cta * 1024 + 512 + tid] = bo;
    }

    // epilogue constants for my 2 rows / 2 cols
    const int r0g = m0 + wmh * 16 + g, r8g = r0g + 8;
    const float bias_g = b_ih[r0g] + b_hh[r0g], bias_8 = b_ih[r8g] + b_hh[r8g];
    const float wih_g = W_ih[r0g], wih_8 = W_ih[r8g];
    const float wout_g = W_out[r0g], wout_8 = W_out[r8g];

    // ---- one-time grid barrier ----
    __threadfence();
    __syncthreads();
    if (tid == 0) g_flags[cta] = base_g + 1;
    if (tid < 32) {
        const int tgt = base_g + 1;
        bool ok;
        do {
            int a = g_flags[tid];
            int b = g_flags[tid + 32];
            int c = g_flags[tid + 64];
            int d = g_flags[tid + 96];
            ok = (a >= tgt) & (b >= tgt) & (c >= tgt) & (d >= tgt);
        } while (!__all_sync(0xffffffffu, ok));
        __threadfence();
    }
    __syncthreads();

    const int barid = 1 + w;             // named barrier per pair (64 threads)
    const int myflag = mi * 2 + wmh;

#pragma unroll 1
    for (int t = 0; t < TT; t++) {
        const int rbuf = (t + 1) & 1, wbuf = t & 1;
        const char* srcB = (const char*)&g_hf[rbuf][nb][0][0][0];
        const int tgt = base_d + t;

        // x for my 2 cols
        const float* xsrc = (t == 0) ? init_in : (targets + (size_t)(t - 1) * BB);
        const float xv0 = __ldg(&xsrc[bb0 + w * 8 + 2 * tq]);
        const float xv1 = __ldg(&xsrc[bb0 + w * 8 + 2 * tq + 1]);

        // poll: chunk c (16 kk) needs 16 contiguous warp-flags [nb][w][16c..]
        auto poll = [&](int c) {
            const volatile int* f = &g_dw2[nb][w][16 * c];
            int r[16];
            bool ok;
            do {
                ldvol4(r, f); ldvol4(r + 4, f + 4);
                ldvol4(r + 8, f + 8); ldvol4(r + 12, f + 12);
                ok = true;
#pragma unroll
                for (int i = 0; i < 16; i++) ok &= (r[i] >= tgt);
            } while (!ok);
            __threadfence();
        };
        // cp.async chunk j (4 KB: kk 16j..16j+15, oct w) into parity p
        auto cpchunk = [&](int j, int p) {
            const uint32_t dst = sb + OFF_B + w * 8192 + p * 4096;
#pragma unroll
            for (int i = 0; i < 8; i++) {
                const int flat = i * 32 + lane;          // 0..255 (16B units)
                const int kkl  = flat >> 4;              // 0..15
                const int inr  = (flat & 15) * 16;
                asm volatile("cp.async.cg.shared.global [%0], [%1], 16;"
                             :: "r"(dst + kkl * 256 + inr),
                                "l"(srcB + (size_t)(((16 * j + kkl) * 8 + w) * 256 + inr)));
            }
            asm volatile("cp.async.commit_group;" ::: "memory");
        };

        // prologue: wmh0 readies chunk 0; wmh1 verifies chunk 1 flags
        if (wmh == 0) {
            poll(0); cpchunk(0, 0);
            asm volatile("cp.async.wait_group 0;" ::: "memory");
        } else {
            poll(1);
        }

        float accH[4], accL[4];
#pragma unroll
        for (int e = 0; e < 4; e++) { accH[e] = 0.f; accL[e] = 0.f; }

#pragma unroll 1
        for (int j = 0; j < 4; j++) {
            asm volatile("bar.sync %0, 64;" :: "r"(barid) : "memory");
            // wmh0: cp chunk j+1 (flags verified by wmh1 one chunk ago)
            if (j < 3 && wmh == 0) cpchunk(j + 1, (j + 1) & 1);
            // wmh1: verify flags for chunk j+2 (lookahead)
            if (j < 2 && wmh == 1) poll(j + 2);

            const int bB = OFF_B + w * 8192 + (j & 1) * 4096 + lane * 8;
#pragma unroll
            for (int k = 0; k < 16; k++) {
                const int kk = j * 16 + k;
                const int ab = (wmh * 64 + kk) * 512 + lane * 16;
                uint4 Ah = *reinterpret_cast<const uint4*>(smem + ab);
                uint4 Al = *reinterpret_cast<const uint4*>(smem + OFF_ALO + ab);
                uint2 V  = *reinterpret_cast<const uint2*>(smem + bB + k * 256);
                uint32_t Bf[2] = {V.x, V.y};
                mma16816h(accH, &Ah.x, Bf);
                mma16816h(accL, &Al.x, Bf);
            }
            if (j < 3 && wmh == 0)
                asm volatile("cp.async.wait_group 0;" ::: "memory");
        }

        // ---- epilogue (warp-autonomous): tanh, publish, flag, then y ----
        float hg0 = ftanh(accH[0] + accL[0] + fmaf(xv0, wih_g, bias_g));
        float hg1 = ftanh(accH[1] + accL[1] + fmaf(xv1, wih_g, bias_g));
        float h80 = ftanh(accH[2] + accL[2] + fmaf(xv0, wih_8, bias_8));
        float h81 = ftanh(accH[3] + accL[3] + fmaf(xv1, wih_8, bias_8));

        const float hgv[2] = {hg0, hg1};
        const float h8v[2] = {h80, h81};
#pragma unroll
        for (int c = 0; c < 2; c++) {
            uint32_t P1 = (uint32_t)hbits(hgv[c]) | ((uint32_t)hbits(h8v[c]) << 16);
            uint32_t q1 = __shfl_xor_sync(0xffffffffu, P1, 4);
            if ((g & 1) == 0) {
                uint2 u;
                u.x = __byte_perm(P1, q1, 0x5410);   // slot0: rows g,g+1
                u.y = __byte_perm(P1, q1, 0x7632);   // slot1: rows g+8,g+9
                g_hf[wbuf][nb][mi * 2 + wmh][w][(2 * tq + c) * 4 + (g >> 1)] = u;
            }
        }
        __threadfence();
        __syncwarp();
        if (lane == 0) g_dw2[nb][w][myflag] = base_d + t + 1;

        // y partials after the flag (off the recurrence critical path)
        float yp0 = hg0 * wout_g + h80 * wout_8;
        float yp1 = hg1 * wout_g + h81 * wout_8;
#pragma unroll
        for (int off = 4; off < 32; off <<= 1) {
            yp0 += __shfl_xor_sync(0xffffffffu, yp0, off);
            yp1 += __shfl_xor_sync(0xffffffffu, yp1, off);
        }
        if (lane < 4) {
            atomicAdd(&out[(size_t)t * BB + bb0 + w * 8 + 2 * lane],     yp0);
            atomicAdd(&out[(size_t)t * BB + bb0 + w * 8 + 2 * lane + 1], yp1);
        }
    }
}

extern "C" void kernel_launch(void* const* d_in, const int* in_sizes, int n_in,
                              void* d_out, int out_size) {
    const float* init_in = (const float*)d_in[0];
    const float* hidden0 = (const float*)d_in[1];
    const float* targets = (const float*)d_in[2];
    const float* W_ih    = (const float*)d_in[3];
    const float* W_hh    = (const float*)d_in[4];
    const float* b_ih    = (const float*)d_in[5];
    const float* b_hh    = (const float*)d_in[6];
    const float* W_out   = (const float*)d_in[7];
    const float* b_out   = (const float*)d_in[8];
    float* out = (float*)d_out;

    cudaFuncSetAttribute(rnn_decoder_kernel,
                         cudaFuncAttributeMaxDynamicSharedMemorySize, SMEM_SZ);
    rnn_decoder_kernel<<<NCTA, NTHR, SMEM_SZ>>>(init_in, hidden0, targets, W_ih,
                                                W_hh, b_ih, b_hh, W_out, b_out,
                                                out);
}

// round 14
// speedup vs baseline: 1.8748x; 1.1752x over previous
#include <cuda_runtime.h>
#include <cuda_fp16.h>
#include <math.h>
#include <stdint.h>

// ---------------- problem constants ----------------
#define BB   256
#define TT   512
#define HH   1024
#define NCTA 128
#define NTHR 512      // 16 warps = wmh(2) x wq(2) x ks(4)

// 128 CTAs = 32 mi (32 neurons) x 4 nb (64 batch); K split 4-way inside CTA.
// SMEM: A frags (W hi 64K | lo 64K fp16) | 8 group B bufs (2 x 4K each) | red
#define OFF_ALO 65536
#define OFF_B   131072
#define OFF_RED 196608
#define SMEM_SZ 221184

// ---------------- device globals ----------------
// h in fp16 B-frag order: [buf][nb][kk 64][oct 8][lane 32] uint2
__device__ __align__(16) uint2 g_hf[2][4][64][8][32];    // 1 MB
// publish flags: [nb][wq][kk-rowgroup 64]
__device__ volatile int g_dw3[4][2][64];
__device__ volatile int g_flags[NCTA];                   // one-time init barrier

__device__ __forceinline__ uint32_t pack_hf(float x, float y) {
    __half2 v = __floats2half2_rn(x, y);
    return *reinterpret_cast<uint32_t*>(&v);
}
__device__ __forceinline__ unsigned short hbits(float x) {
    return __half_as_ushort(__float2half_rn(x));
}
__device__ __forceinline__ float hup(unsigned short u) {
    return __half2float(__ushort_as_half(u));
}
__device__ __forceinline__ void mma16816h(float* c, const uint32_t* a,
                                          const uint32_t* b) {
    asm volatile(
        "mma.sync.aligned.m16n8k16.row.col.f32.f16.f16.f32 "
        "{%0,%1,%2,%3}, {%4,%5,%6,%7}, {%8,%9}, {%0,%1,%2,%3};"
        : "+f"(c[0]), "+f"(c[1]), "+f"(c[2]), "+f"(c[3])
        : "r"(a[0]), "r"(a[1]), "r"(a[2]), "r"(a[3]), "r"(b[0]), "r"(b[1]));
}
__device__ __forceinline__ float ftanh(float x) {
    float e = __expf(2.f * x);
    return 1.f - __fdividef(2.f, e + 1.f);
}
__device__ __forceinline__ void ldvol4(int* r, const volatile int* p) {
    asm volatile("ld.volatile.global.v4.u32 {%0,%1,%2,%3}, [%4];"
                 : "=r"(r[0]), "=r"(r[1]), "=r"(r[2]), "=r"(r[3])
                 : "l"(p));
}

extern "C" __global__ void __launch_bounds__(NTHR, 1)
rnn_decoder_kernel(const float* __restrict__ init_in,   // [B,1]
                   const float* __restrict__ hidden0,   // [B,H]
                   const float* __restrict__ targets,   // [T,B,1]
                   const float* __restrict__ W_ih,      // [H,1]
                   const float* __restrict__ W_hh,      // [H,H]
                   const float* __restrict__ b_ih,      // [H]
                   const float* __restrict__ b_hh,      // [H]
                   const float* __restrict__ W_out,     // [1,H]
                   const float* __restrict__ b_out,     // [1]
                   float* __restrict__ out)             // [T,B,1]
{
    extern __shared__ __align__(16) char smem[];
    uint32_t sb;
    asm("{ .reg .u64 t; cvta.to.shared.u64 t, %1; cvt.u32.u64 %0, t; }"
        : "=r"(sb) : "l"(smem));

    const int tid  = threadIdx.x;
    const int cta  = blockIdx.x;
    const int wid  = tid >> 5;
    const int lane = tid & 31;
    const int g    = lane >> 2;
    const int tq   = lane & 3;
    const int wmh  = wid & 1;            // M half (16 rows)
    const int grp  = wid >> 1;           // 0..7
    const int wq   = grp >> 2;           // col half (32 cols)
    const int ks   = grp & 3;            // K slice (256 n's = 16 kk)

    const int mi  = cta >> 2;            // 0..31
    const int nb  = cta & 3;             // 0..3
    const int m0  = mi * 32;
    const int bb0 = nb * 64;

    const int base_g = g_flags[cta];
    const int base_d = g_dw3[nb][wq][mi * 2 + wmh];

    // ---- one-time: A fragments (W hi+lo fp16) in exact mma lane order ----
    {
        const int r0 = m0 + wmh * 16 + g;
        const int r1 = r0 + 8;
        for (int jj = 0; jj < 8; jj++) {
            const int kk = grp + 8 * jj;                 // 0..63
            const int c  = kk * 16 + 2 * tq;
            float w00 = W_hh[(size_t)r0 * HH + c];
            float w01 = W_hh[(size_t)r0 * HH + c + 1];
            float w04 = W_hh[(size_t)r0 * HH + c + 8];
            float w05 = W_hh[(size_t)r0 * HH + c + 9];
            float w10 = W_hh[(size_t)r1 * HH + c];
            float w11 = W_hh[(size_t)r1 * HH + c + 1];
            float w14 = W_hh[(size_t)r1 * HH + c + 8];
            float w15 = W_hh[(size_t)r1 * HH + c + 9];
            uint4 hi, lo;
            hi.x = pack_hf(w00, w01);
            hi.y = pack_hf(w10, w11);
            hi.z = pack_hf(w04, w05);
            hi.w = pack_hf(w14, w15);
            lo.x = pack_hf(w00 - hup(hbits(w00)), w01 - hup(hbits(w01)));
            lo.y = pack_hf(w10 - hup(hbits(w10)), w11 - hup(hbits(w11)));
            lo.z = pack_hf(w04 - hup(hbits(w04)), w05 - hup(hbits(w05)));
            lo.w = pack_hf(w14 - hup(hbits(w14)), w15 - hup(hbits(w15)));
            const int ob = (wmh * 64 + kk) * 512 + lane * 16;
            *reinterpret_cast<uint4*>(smem + ob)           = hi;
            *reinterpret_cast<uint4*>(smem + OFF_ALO + ob) = lo;
        }
    }

    // ---- one-time: publish h0 slice into g_hf[1] ----
    {
        const int pwmh = tid >> 8;
        const int poct = (tid >> 5) & 7;
        const int pln  = tid & 31;
        const int pcol = pln >> 2;
        const int pg   = (pln & 3) * 2;
        const int col  = bb0 + poct * 8 + pcol;
        const int rA   = m0 + pwmh * 16 + pg;
        float va = hidden0[(size_t)col * HH + rA];
        float vb = hidden0[(size_t)col * HH + rA + 1];
        float vc = hidden0[(size_t)col * HH + rA + 8];
        float vd = hidden0[(size_t)col * HH + rA + 9];
        uint2 u;
        u.x = (uint32_t)hbits(va) | ((uint32_t)hbits(vb) << 16);
        u.y = (uint32_t)hbits(vc) | ((uint32_t)hbits(vd) << 16);
        g_hf[1][nb][mi * 2 + pwmh][poct][pcol * 4 + (pg >> 1)] = u;
    }
    // ---- one-time: out init to b_out ----
    {
        const float bo = b_out[0];
        out[(size_t)cta * 1024 + tid]       = bo;
        out[(size_t)cta * 1024 + 512 + tid] = bo;
    }

    // epilogue constants for my 2 rows
    const int r0g = m0 + wmh * 16 + g, r8g = r0g + 8;
    const float bias_g = b_ih[r0g] + b_hh[r0g], bias_8 = b_ih[r8g] + b_hh[r8g];
    const float wih_g = W_ih[r0g], wih_8 = W_ih[r8g];
    const float wout_g = W_out[r0g], wout_8 = W_out[r8g];

    // ---- one-time grid barrier ----
    __threadfence();
    __syncthreads();
    if (tid == 0) g_flags[cta] = base_g + 1;
    if (tid < 32) {
        const int tgt = base_g + 1;
        bool ok;
        do {
            int a = g_flags[tid];
            int b = g_flags[tid + 32];
            int c = g_flags[tid + 64];
            int d = g_flags[tid + 96];
            ok = (a >= tgt) & (b >= tgt) & (c >= tgt) & (d >= tgt);
        } while (!__all_sync(0xffffffffu, ok));
        __threadfence();
    }
    __syncthreads();

    const int barid = 1 + grp;           // per-(wq,ks) group bar (64 thr)
    const int redid = 9 + wmh * 2 + wq;  // per-(wmh,wq) reduce bar (128 thr)
    float* redf = reinterpret_cast<float*>(smem + OFF_RED) +
                  (wmh * 2 + wq) * 1536;                 // 3 slices x 512 floats

#pragma unroll 1
    for (int t = 0; t < TT; t++) {
        const int rbuf = (t + 1) & 1, wbuf = t & 1;
        const char* srcB = (const char*)&g_hf[rbuf][nb][0][0][0];
        const int tgt = base_d + t;

        // x for ks0 epilogue cols (8 per lane)
        float xv[4][2];
        if (ks == 0) {
            const float* xsrc = (t == 0) ? init_in
                                         : (targets + (size_t)(t - 1) * BB);
#pragma unroll
            for (int o = 0; o < 4; o++) {
                xv[o][0] = __ldg(&xsrc[bb0 + wq * 32 + o * 8 + 2 * tq]);
                xv[o][1] = __ldg(&xsrc[bb0 + wq * 32 + o * 8 + 2 * tq + 1]);
            }
        }

        // poll chunk c: 4 contiguous flags [nb][wq][16ks+4c..]
        auto poll = [&](int c) {
            const volatile int* f = &g_dw3[nb][wq][16 * ks + 4 * c];
            int r[4];
            bool ok;
            do {
                ldvol4(r, f);
                ok = (r[0] >= tgt) & (r[1] >= tgt) & (r[2] >= tgt) & (r[3] >= tgt);
            } while (!ok);
            __threadfence();
        };
        // cp.async chunk j (4 KB: 4 kk x 4 oct) into parity p
        auto cpchunk = [&](int j, int p) {
            const uint32_t dst = sb + OFF_B + grp * 8192 + p * 4096;
#pragma unroll
            for (int i = 0; i < 8; i++) {
                const int flat = i * 32 + lane;          // 0..255
                const int seg  = flat >> 4;              // 0..15
                const int kkL  = seg >> 2;
                const int oct  = seg & 3;
                const int inr  = (flat & 15) * 16;
                asm volatile("cp.async.cg.shared.global [%0], [%1], 16;"
                             :: "r"(dst + seg * 256 + inr),
                                "l"(srcB + (size_t)(((16 * ks + 4 * j + kkL) * 8 +
                                                    4 * wq + oct) * 256 + inr)));
            }
            asm volatile("cp.async.commit_group;" ::: "memory");
        };

        if (wmh == 0) {
            poll(0); cpchunk(0, 0);
            asm volatile("cp.async.wait_group 0;" ::: "memory");
        } else {
            poll(1);
        }

        float accH[4][4], accL[4][4];
#pragma unroll
        for (int o = 0; o < 4; o++)
#pragma unroll
            for (int e = 0; e < 4; e++) { accH[o][e] = 0.f; accL[o][e] = 0.f; }

#pragma unroll 1
        for (int j = 0; j < 4; j++) {
            asm volatile("bar.sync %0, 64;" :: "r"(barid) : "memory");
            if (j < 3 && wmh == 0) cpchunk(j + 1, (j + 1) & 1);
            if (j < 2 && wmh == 1) poll(j + 2);

            const int bB = OFF_B + grp * 8192 + (j & 1) * 4096 + lane * 8;
#pragma unroll
            for (int k4 = 0; k4 < 4; k4++) {
                const int kk = 16 * ks + 4 * j + k4;
                const int ab = (wmh * 64 + kk) * 512 + lane * 16;
                uint4 Ah = *reinterpret_cast<const uint4*>(smem + ab);
                uint4 Al = *reinterpret_cast<const uint4*>(smem + OFF_ALO + ab);
#pragma unroll
                for (int o = 0; o < 4; o++) {
                    uint2 V = *reinterpret_cast<const uint2*>(
                        smem + bB + (k4 * 4 + o) * 256);
                    uint32_t Bf[2] = {V.x, V.y};
                    mma16816h(accH[o], &Ah.x, Bf);
                    mma16816h(accL[o], &Al.x, Bf);
                }
            }
            if (j < 3 && wmh == 0)
                asm volatile("cp.async.wait_group 0;" ::: "memory");
        }

        // ---- cross-ks reduction ----
        float s[4][4];
#pragma unroll
        for (int o = 0; o < 4; o++)
#pragma unroll
            for (int e = 0; e < 4; e++) s[o][e] = accH[o][e] + accL[o][e];

        asm volatile("bar.sync %0, 128;" :: "r"(redid) : "memory");   // barA
        if (ks) {
            float* red = redf + (ks - 1) * 512;
#pragma unroll
            for (int f = 0; f < 16; f++) red[f * 32 + lane] = s[f >> 2][f & 3];
        }
        asm volatile("bar.sync %0, 128;" :: "r"(redid) : "memory");   // barB

        if (ks == 0) {
#pragma unroll
            for (int f = 0; f < 16; f++)
                s[f >> 2][f & 3] += redf[f * 32 + lane] +
                                    redf[512 + f * 32 + lane] +
                                    redf[1024 + f * 32 + lane];

            float hg[4][2], h8[4][2];
#pragma unroll
            for (int o = 0; o < 4; o++) {
                hg[o][0] = ftanh(s[o][0] + fmaf(xv[o][0], wih_g, bias_g));
                hg[o][1] = ftanh(s[o][1] + fmaf(xv[o][1], wih_g, bias_g));
                h8[o][0] = ftanh(s[o][2] + fmaf(xv[o][0], wih_8, bias_8));
                h8[o][1] = ftanh(s[o][3] + fmaf(xv[o][1], wih_8, bias_8));
            }
            // publish h' frags (even-g lanes)
#pragma unroll
            for (int o = 0; o < 4; o++)
#pragma unroll
                for (int c = 0; c < 2; c++) {
                    uint32_t P1 = (uint32_t)hbits(hg[o][c]) |
                                  ((uint32_t)hbits(h8[o][c]) << 16);
                    uint32_t q1 = __shfl_xor_sync(0xffffffffu, P1, 4);
                    if ((g & 1) == 0) {
                        uint2 u;
                        u.x = __byte_perm(P1, q1, 0x5410);
                        u.y = __byte_perm(P1, q1, 0x7632);
                        g_hf[wbuf][nb][mi * 2 + wmh][4 * wq + o]
                            [(2 * tq + c) * 4 + (g >> 1)] = u;
                    }
                }
            __threadfence();
            __syncwarp();
            if (lane == 0) g_dw3[nb][wq][mi * 2 + wmh] = base_d + t + 1;

            // y partials (off critical path)
            float yp[4][2];
#pragma unroll
            for (int o = 0; o < 4; o++)
#pragma unroll
                for (int c = 0; c < 2; c++)
                    yp[o][c] = hg[o][c] * wout_g + h8[o][c] * wout_8;
#pragma unroll
            for (int off = 4; off < 32; off <<= 1)
#pragma unroll
                for (int o = 0; o < 4; o++)
#pragma unroll
                    for (int c = 0; c < 2; c++)
                        yp[o][c] += __shfl_xor_sync(0xffffffffu, yp[o][c], off);
            if (lane < 4) {
#pragma unroll
                for (int o = 0; o < 4; o++)
#pragma unroll
                    for (int c = 0; c < 2; c++)
                        atomicAdd(&out[(size_t)t * BB + bb0 + wq * 32 + o * 8 +
                                       2 * lane + c], yp[o][c]);
            }
        }
    }
}

extern "C" void kernel_launch(void* const* d_in, const int* in_sizes, int n_in,
                              void* d_out, int out_size) {
    const float* init_in = (const float*)d_in[0];
    const float* hidden0 = (const float*)d_in[1];
    const float* targets = (const float*)d_in[2];
    const float* W_ih    = (const float*)d_in[3];
    const float* W_hh    = (const float*)d_in[4];
    const float* b_ih    = (const float*)d_in[5];
    const float* b_hh    = (const float*)d_in[6];
    const float* W_out   = (const float*)d_in[7];
    const float* b_out   = (const float*)d_in[8];
    float* out = (float*)d_out;

    cudaFuncSetAttribute(rnn_decoder_kernel,
                         cudaFuncAttributeMaxDynamicSharedMemorySize, SMEM_SZ);
    rnn_decoder_kernel<<<NCTA, NTHR, SMEM_SZ>>>(init_in, hidden0, targets, W_ih,
                                                W_hh, b_ih, b_hh, W_out, b_out,
                                                out);
}